// round 2
// baseline (speedup 1.0000x reference)
#include <cuda_runtime.h>

// ---------------------------------------------------------------------------
// AuxSeLoss: loss = mean(bce(out0,t)) + 0.4*mean(bce(out1,t)) + 0.2*mean(bce(out2, se_t))
// se_t[b,c] = 1 if any element of targets[b] falls in histc bin c (21 bins over [0,20]).
// Shapes: out0/out1/targets [16,21,256,256] f32, out2 [16,21] f32, output scalar f32.
// ---------------------------------------------------------------------------

namespace {
constexpr int   NC           = 21;
constexpr int   NB           = 16;
constexpr long long HW       = 256LL * 256LL;
constexpr long long CHW      = (long long)NC * HW;      // 1376256
constexpr long long NTOT     = (long long)NB * CHW;     // 22020096
constexpr int   NV4          = (int)(NTOT / 4);         // 5505024  (divisible by 4)
constexpr int   V4_PER_BATCH = (int)(CHW / 4);          // 344064
constexpr int   GRID         = 1776;                    // 148 SMs * 12
constexpr int   THREADS      = 256;
}

__device__ double       g_sum0;
__device__ double       g_sum1;
__device__ unsigned int g_flags[NB];

__global__ void init_kernel() {
    if (threadIdx.x == 0) { g_sum0 = 0.0; g_sum1 = 0.0; }
    if (threadIdx.x < NB) g_flags[threadIdx.x] = 0u;
}

__device__ __forceinline__ float bce_term(float x, float t) {
    // max(x,0) - x*t + log1p(exp(-|x|)); fast-math variants are far below 1e-3 tol.
    float e = __expf(-fabsf(x));
    return fmaxf(x, 0.0f) - x * t + __logf(1.0f + e);
}

__global__ __launch_bounds__(THREADS) void main_kernel(
    const float4* __restrict__ o0,
    const float4* __restrict__ o1,
    const float4* __restrict__ tg) {

    __shared__ unsigned int flagsS[NB];
    __shared__ float red0[THREADS / 32];
    __shared__ float red1[THREADS / 32];

    if (threadIdx.x < NB) flagsS[threadIdx.x] = 0u;
    __syncthreads();

    // Contiguous chunk per block: keeps each thread inside 1-2 batches so the
    // histogram "seen" mask flushes at most twice per thread.
    const int chunk = (NV4 + (int)gridDim.x - 1) / (int)gridDim.x;
    const int start = (int)blockIdx.x * chunk;
    const int end   = min(start + chunk, NV4);

    float s0 = 0.0f, s1 = 0.0f;
    unsigned int seen = 0u;
    int cur_b = -1;
    const float bin_w = 20.0f / 21.0f;   // matches jnp (n_classes-1)/n_classes in f32

    for (int i = start + (int)threadIdx.x; i < end; i += THREADS) {
        float4 a  = o0[i];
        float4 b4 = o1[i];
        float4 t4 = tg[i];

        s0 += bce_term(a.x,  t4.x) + bce_term(a.y,  t4.y)
            + bce_term(a.z,  t4.z) + bce_term(a.w,  t4.w);
        s1 += bce_term(b4.x, t4.x) + bce_term(b4.y, t4.y)
            + bce_term(b4.z, t4.z) + bce_term(b4.w, t4.w);

        int b = i / V4_PER_BATCH;
        if (b != cur_b) {
            if (cur_b >= 0 && seen) atomicOr(&flagsS[cur_b], seen);
            cur_b = b;
            seen = 0u;
        }
        float tv[4] = {t4.x, t4.y, t4.z, t4.w};
        #pragma unroll
        for (int k = 0; k < 4; ++k) {
            float v = tv[k];
            if (v >= 0.0f && v <= 20.0f) {      // histc drops out-of-range
                int idx = (int)floorf(v / bin_w);
                idx = min(max(idx, 0), NC - 1);
                seen |= 1u << idx;
            }
        }
    }
    if (cur_b >= 0 && seen) atomicOr(&flagsS[cur_b], seen);

    // intra-warp reduce
    #pragma unroll
    for (int off = 16; off > 0; off >>= 1) {
        s0 += __shfl_down_sync(0xffffffffu, s0, off);
        s1 += __shfl_down_sync(0xffffffffu, s1, off);
    }
    const int lane = threadIdx.x & 31;
    const int wid  = threadIdx.x >> 5;
    if (lane == 0) { red0[wid] = s0; red1[wid] = s1; }
    __syncthreads();

    if (threadIdx.x < NB) {
        unsigned int f = flagsS[threadIdx.x];
        if (f) atomicOr(&g_flags[threadIdx.x], f);
    }

    if (wid == 0) {
        s0 = (lane < THREADS / 32) ? red0[lane] : 0.0f;
        s1 = (lane < THREADS / 32) ? red1[lane] : 0.0f;
        #pragma unroll
        for (int off = 4; off > 0; off >>= 1) {
            s0 += __shfl_down_sync(0xffffffffu, s0, off);
            s1 += __shfl_down_sync(0xffffffffu, s1, off);
        }
        if (lane == 0) {
            atomicAdd(&g_sum0, (double)s0);
            atomicAdd(&g_sum1, (double)s1);
        }
    }
}

__global__ void final_kernel(const float* __restrict__ o2, float* __restrict__ out) {
    __shared__ float red[12];
    const int tid = (int)threadIdx.x;   // 384 threads

    float v = 0.0f;
    if (tid < NB * NC) {
        int b = tid / NC;
        int c = tid % NC;
        float t = ((g_flags[b] >> c) & 1u) ? 1.0f : 0.0f;
        float x = o2[tid];
        // Use precise expf/log1pf here: only 336 elems, and loss_se gets 0.2 weight.
        v = fmaxf(x, 0.0f) - x * t + log1pf(expf(-fabsf(x)));
    }
    #pragma unroll
    for (int off = 16; off > 0; off >>= 1)
        v += __shfl_down_sync(0xffffffffu, v, off);
    const int lane = tid & 31, wid = tid >> 5;
    if (lane == 0) red[wid] = v;
    __syncthreads();
    if (wid == 0) {
        v = (lane < 12) ? red[lane] : 0.0f;
        #pragma unroll
        for (int off = 8; off > 0; off >>= 1)
            v += __shfl_down_sync(0xffffffffu, v, off);
        if (lane == 0) {
            double loss0 = g_sum0 / (double)NTOT;
            double loss1 = g_sum1 / (double)NTOT;
            double loss_se = (double)v / (double)(NB * NC);
            out[0] = (float)(loss0 + 0.4 * loss1 + 0.2 * loss_se);
        }
    }
}

extern "C" void kernel_launch(void* const* d_in, const int* in_sizes, int n_in,
                              void* d_out, int out_size) {
    (void)in_sizes; (void)n_in; (void)out_size;
    const float4* o0 = (const float4*)d_in[0];
    const float4* o1 = (const float4*)d_in[1];
    const float*  o2 = (const float*) d_in[2];
    const float4* tg = (const float4*)d_in[3];

    init_kernel<<<1, 32>>>();
    main_kernel<<<GRID, THREADS>>>(o0, o1, tg);
    final_kernel<<<1, 384>>>(o2, (float*)d_out);
}

// round 4
// speedup vs baseline: 2.1224x; 2.1224x over previous
#include <cuda_runtime.h>

// ---------------------------------------------------------------------------
// AuxSeLoss: loss = mean(bce(out0,t)) + 0.4*mean(bce(out1,t)) + 0.2*mean(bce(out2, se_t))
// se_t[b,c] = 1 if any element of targets[b] falls in histc bin c (21 bins over [0,20]).
// Shapes: out0/out1/targets [16,21,256,256] f32, out2 [16,21] f32, output scalar f32.
//
// Static decomposition: 16 batches x 112 blocks; each block covers exactly
// 3072 float4 (= 12 iters x 256 threads) inside one batch. No divides, no
// bounds checks, no batch-crossing logic in the hot loop. Per-block partials
// (full overwrite) replace zero-initialized atomics -> no init kernel.
// ---------------------------------------------------------------------------

namespace {
constexpr int   NC            = 21;
constexpr int   NB            = 16;
constexpr long long HW        = 256LL * 256LL;
constexpr long long CHW       = (long long)NC * HW;     // 1376256
constexpr long long NTOT      = (long long)NB * CHW;    // 22020096
constexpr int   V4_PER_BATCH  = (int)(CHW / 4);         // 344064
constexpr int   BLK_PER_BATCH = 112;
constexpr int   GRID          = NB * BLK_PER_BATCH;     // 1792
constexpr int   THREADS       = 256;
constexpr int   CHUNK_V4      = V4_PER_BATCH / BLK_PER_BATCH;  // 3072
constexpr int   ITERS         = CHUNK_V4 / THREADS;            // 12
static_assert(V4_PER_BATCH % BLK_PER_BATCH == 0, "");
static_assert(CHUNK_V4 % THREADS == 0, "");
}

__device__ float        g_part0[GRID];
__device__ float        g_part1[GRID];
__device__ unsigned int g_flagp[GRID];

__device__ __forceinline__ float bce_term(float x, float t) {
    // max(x,0) - x*t + log1p(exp(-|x|)) with HW EX2/LG2 intrinsics.
    float e = __expf(-fabsf(x));
    return fmaxf(x, 0.0f) - x * t + __logf(1.0f + e);
}

__global__ __launch_bounds__(THREADS) void main_kernel(
    const float4* __restrict__ o0,
    const float4* __restrict__ o1,
    const float4* __restrict__ tg) {

    __shared__ unsigned int flagS;
    __shared__ float red0[THREADS / 32];
    __shared__ float red1[THREADS / 32];
    if (threadIdx.x == 0) flagS = 0u;
    __syncthreads();

    const int blk      = (int)blockIdx.x;
    const int batch    = blk / BLK_PER_BATCH;            // once, not per-iter
    const int bInBatch = blk - batch * BLK_PER_BATCH;
    const int base     = batch * V4_PER_BATCH + bInBatch * CHUNK_V4 + (int)threadIdx.x;

    float s0a = 0.0f, s0b = 0.0f, s1a = 0.0f, s1b = 0.0f;
    unsigned int seen = 0u;
    const float inv_bw = 21.0f / 20.0f;   // 1 / ((n_classes-1)/n_classes)

    #pragma unroll 4
    for (int it = 0; it < ITERS; ++it) {
        const int i = base + it * THREADS;
        float4 a  = o0[i];
        float4 b4 = o1[i];
        float4 t4 = tg[i];

        s0a += bce_term(a.x,  t4.x) + bce_term(a.y,  t4.y);
        s0b += bce_term(a.z,  t4.z) + bce_term(a.w,  t4.w);
        s1a += bce_term(b4.x, t4.x) + bce_term(b4.y, t4.y);
        s1b += bce_term(b4.z, t4.z) + bce_term(b4.w, t4.w);

        float tv[4] = {t4.x, t4.y, t4.z, t4.w};
        #pragma unroll
        for (int k = 0; k < 4; ++k) {
            float v = tv[k];
            if (v >= 0.0f && v <= 20.0f) {            // histc drops out-of-range
                int idx = (int)floorf(v * inv_bw);
                idx = min(max(idx, 0), NC - 1);
                seen |= 1u << idx;
            }
        }
    }

    float s0 = s0a + s0b;
    float s1 = s1a + s1b;

    // intra-warp reduce
    #pragma unroll
    for (int off = 16; off > 0; off >>= 1) {
        s0   += __shfl_down_sync(0xffffffffu, s0, off);
        s1   += __shfl_down_sync(0xffffffffu, s1, off);
        seen |= __shfl_down_sync(0xffffffffu, seen, off);
    }
    const int lane = threadIdx.x & 31;
    const int wid  = threadIdx.x >> 5;
    if (lane == 0) {
        red0[wid] = s0;
        red1[wid] = s1;
        if (seen) atomicOr(&flagS, seen);
    }
    __syncthreads();

    if (wid == 0) {
        s0 = (lane < THREADS / 32) ? red0[lane] : 0.0f;
        s1 = (lane < THREADS / 32) ? red1[lane] : 0.0f;
        #pragma unroll
        for (int off = 4; off > 0; off >>= 1) {
            s0 += __shfl_down_sync(0xffffffffu, s0, off);
            s1 += __shfl_down_sync(0xffffffffu, s1, off);
        }
        if (lane == 0) {
            g_part0[blk] = s0;       // full overwrite -> no init kernel needed
            g_part1[blk] = s1;
            g_flagp[blk] = flagS;
        }
    }
}

__global__ __launch_bounds__(1024) void final_kernel(
    const float* __restrict__ o2, float* __restrict__ out) {

    __shared__ unsigned int flagsS[NB];
    __shared__ double redA[32];
    __shared__ float  redB[32];

    const int tid  = (int)threadIdx.x;   // 1024 threads
    const int lane = tid & 31;
    const int wid  = tid >> 5;

    if (tid < NB) flagsS[tid] = 0u;
    __syncthreads();

    // Phase 1: fold per-block partials (1792 of each) + OR flags per batch.
    double d01 = 0.0;   // s0 + 0.4*s1 folded together
    for (int i = tid; i < GRID; i += 1024) {
        d01 += (double)g_part0[i] + 0.4 * (double)g_part1[i];
        unsigned int f = g_flagp[i];
        if (f) atomicOr(&flagsS[i / BLK_PER_BATCH], f);
    }
    #pragma unroll
    for (int off = 16; off > 0; off >>= 1)
        d01 += __shfl_down_sync(0xffffffffu, d01, off);
    if (lane == 0) redA[wid] = d01;
    __syncthreads();   // also publishes flagsS

    // Phase 2: se BCE over out2 [16,21] with targets from flagsS.
    float v = 0.0f;
    if (tid < NB * NC) {
        int b = tid / NC;
        int c = tid - b * NC;
        float t = ((flagsS[b] >> c) & 1u) ? 1.0f : 0.0f;
        float x = o2[tid];
        v = fmaxf(x, 0.0f) - x * t + log1pf(expf(-fabsf(x)));
    }
    #pragma unroll
    for (int off = 16; off > 0; off >>= 1)
        v += __shfl_down_sync(0xffffffffu, v, off);
    if (lane == 0) redB[wid] = v;
    __syncthreads();

    if (wid == 0) {
        double dd = (lane < 32) ? redA[lane] : 0.0;
        float  vv = (lane < 32) ? redB[lane] : 0.0f;
        #pragma unroll
        for (int off = 16; off > 0; off >>= 1) {
            dd += __shfl_down_sync(0xffffffffu, dd, off);
            vv += __shfl_down_sync(0xffffffffu, vv, off);
        }
        if (lane == 0) {
            double loss01  = dd / (double)NTOT;
            double loss_se = (double)vv / (double)(NB * NC);
            out[0] = (float)(loss01 + 0.2 * loss_se);
        }
    }
}

extern "C" void kernel_launch(void* const* d_in, const int* in_sizes, int n_in,
                              void* d_out, int out_size) {
    (void)in_sizes; (void)n_in; (void)out_size;
    const float4* o0 = (const float4*)d_in[0];
    const float4* o1 = (const float4*)d_in[1];
    const float*  o2 = (const float*) d_in[2];
    const float4* tg = (const float4*)d_in[3];

    main_kernel<<<GRID, THREADS>>>(o0, o1, tg);
    final_kernel<<<1, 1024>>>(o2, (float*)d_out);
}

// round 7
// speedup vs baseline: 2.1773x; 1.0259x over previous
#include <cuda_runtime.h>

// ---------------------------------------------------------------------------
// AuxSeLoss: loss = mean(bce(out0,t)) + 0.4*mean(bce(out1,t)) + 0.2*mean(bce(out2, se_t))
// se_t[b,c] = 1 if any element of targets[b] falls in histc bin c (21 bins over [0,20]).
// Shapes: out0/out1/targets [16,21,256,256] f32, out2 [16,21] f32, output scalar f32.
//
// Single fused kernel: 16 batches x 112 blocks; each block covers exactly
// 3072 float4 (= 12 iters x 256 threads) inside one batch. Per-block partials
// published with st.global.cg; last block (threadfence + counter) finalizes.
// R5/R6 bug was NOT coherence: the se-BCE phase guarded with tid<336 but the
// fused block has 256 threads, dropping elements 256..335. Now a strided loop.
// ---------------------------------------------------------------------------

namespace {
constexpr int   NC            = 21;
constexpr int   NB            = 16;
constexpr long long HW        = 256LL * 256LL;
constexpr long long CHW       = (long long)NC * HW;     // 1376256
constexpr long long NTOT      = (long long)NB * CHW;    // 22020096
constexpr int   V4_PER_BATCH  = (int)(CHW / 4);         // 344064
constexpr int   BLK_PER_BATCH = 112;
constexpr int   GRID          = NB * BLK_PER_BATCH;     // 1792
constexpr int   THREADS       = 256;
constexpr int   NWARP         = THREADS / 32;
constexpr int   CHUNK_V4      = V4_PER_BATCH / BLK_PER_BATCH;  // 3072
constexpr int   ITERS         = CHUNK_V4 / THREADS;            // 12
static_assert(V4_PER_BATCH % BLK_PER_BATCH == 0, "");
static_assert(CHUNK_V4 % THREADS == 0, "");
}

__device__ float        g_part0[GRID];
__device__ float        g_part1[GRID];
__device__ unsigned int g_flagp[GRID];
__device__ unsigned int g_count;          // zero at load; reset by finalizer

__device__ __forceinline__ float bce_term(float x, float t) {
    // max(x,0) - x*t + log1p(exp(-|x|)) with HW EX2/LG2 intrinsics.
    float e = __expf(-fabsf(x));
    return fmaxf(x, 0.0f) - x * t + __logf(1.0f + e);
}

__global__ __launch_bounds__(THREADS) void fused_kernel(
    const float4* __restrict__ o0,
    const float4* __restrict__ o1,
    const float4* __restrict__ tg,
    const float*  __restrict__ o2,
    float*        __restrict__ out) {

    __shared__ unsigned int flagS;
    __shared__ float red0[NWARP];
    __shared__ float red1[NWARP];
    __shared__ int   isLastS;

    const int tid  = (int)threadIdx.x;
    const int lane = tid & 31;
    const int wid  = tid >> 5;
    if (tid == 0) flagS = 0u;
    __syncthreads();

    const int blk      = (int)blockIdx.x;
    const int batch    = blk / BLK_PER_BATCH;
    const int bInBatch = blk - batch * BLK_PER_BATCH;
    const int base     = batch * V4_PER_BATCH + bInBatch * CHUNK_V4 + tid;

    float s0a = 0.0f, s0b = 0.0f, s1a = 0.0f, s1b = 0.0f;
    unsigned int seen = 0u;
    const float inv_bw = 21.0f / 20.0f;   // 1 / ((n_classes-1)/n_classes)

    #pragma unroll 4
    for (int it = 0; it < ITERS; ++it) {
        const int i = base + it * THREADS;
        float4 a  = __ldcs(&o0[i]);
        float4 b4 = __ldcs(&o1[i]);
        float4 t4 = __ldcs(&tg[i]);

        s0a += bce_term(a.x,  t4.x) + bce_term(a.y,  t4.y);
        s0b += bce_term(a.z,  t4.z) + bce_term(a.w,  t4.w);
        s1a += bce_term(b4.x, t4.x) + bce_term(b4.y, t4.y);
        s1b += bce_term(b4.z, t4.z) + bce_term(b4.w, t4.w);

        float tv[4] = {t4.x, t4.y, t4.z, t4.w};
        #pragma unroll
        for (int k = 0; k < 4; ++k) {
            float v = tv[k];
            if (v >= 0.0f && v <= 20.0f) {            // histc drops out-of-range
                int idx = (int)floorf(v * inv_bw);
                idx = min(max(idx, 0), NC - 1);
                seen |= 1u << idx;
            }
        }
    }

    float s0 = s0a + s0b;
    float s1 = s1a + s1b;

    #pragma unroll
    for (int off = 16; off > 0; off >>= 1) {
        s0   += __shfl_down_sync(0xffffffffu, s0, off);
        s1   += __shfl_down_sync(0xffffffffu, s1, off);
        seen |= __shfl_down_sync(0xffffffffu, seen, off);
    }
    if (lane == 0) {
        red0[wid] = s0;
        red1[wid] = s1;
        if (seen) atomicOr(&flagS, seen);
    }
    __syncthreads();

    if (tid == 0) {
        s0 = red0[0]; s1 = red1[0];
        #pragma unroll
        for (int w = 1; w < NWARP; ++w) { s0 += red0[w]; s1 += red1[w]; }
        // L2-coherent publish (no SM ever holds these lines stale in L1)
        __stcg(&g_part0[blk], s0);
        __stcg(&g_part1[blk], s1);
        __stcg(&g_flagp[blk], flagS);
        __threadfence();                               // order publishes before count
        unsigned int prev = atomicAdd(&g_count, 1u);
        isLastS = (prev == (unsigned int)(GRID - 1));
        if (isLastS) atomicExch(&g_count, 0u);         // reset for next replay
    }
    __syncthreads();
    if (!isLastS) return;

    // ---------------- last block: finalize ----------------
    __threadfence();   // acquire side of the counter handshake

    __shared__ unsigned int flagsF[NB];
    __shared__ double redD[NWARP];
    __shared__ float  redF[NWARP];
    if (tid < NB) flagsF[tid] = 0u;
    __syncthreads();

    double d01 = 0.0;                 // s0 + 0.4*s1 folded
    #pragma unroll
    for (int i = tid; i < GRID; i += THREADS) {
        d01 += (double)__ldcg(&g_part0[i]) + 0.4 * (double)__ldcg(&g_part1[i]);
        unsigned int f = __ldcg(&g_flagp[i]);
        if (f) atomicOr(&flagsF[i / BLK_PER_BATCH], f);
    }
    #pragma unroll
    for (int off = 16; off > 0; off >>= 1)
        d01 += __shfl_down_sync(0xffffffffu, d01, off);
    if (lane == 0) redD[wid] = d01;
    __syncthreads();                  // also publishes flagsF

    // se BCE over ALL 336 out2 elements (strided: 256 threads < 336 elements!)
    float v = 0.0f;
    for (int i = tid; i < NB * NC; i += THREADS) {
        int b = i / NC;
        int c = i - b * NC;
        float t = ((flagsF[b] >> c) & 1u) ? 1.0f : 0.0f;
        float x = o2[i];
        v += fmaxf(x, 0.0f) - x * t + log1pf(expf(-fabsf(x)));
    }
    #pragma unroll
    for (int off = 16; off > 0; off >>= 1)
        v += __shfl_down_sync(0xffffffffu, v, off);
    if (lane == 0) redF[wid] = v;
    __syncthreads();

    if (tid == 0) {
        double dd = 0.0; float vv = 0.0f;
        #pragma unroll
        for (int w = 0; w < NWARP; ++w) { dd += redD[w]; vv += redF[w]; }
        double loss01  = dd / (double)NTOT;
        double loss_se = (double)vv / (double)(NB * NC);
        out[0] = (float)(loss01 + 0.2 * loss_se);
    }
}

extern "C" void kernel_launch(void* const* d_in, const int* in_sizes, int n_in,
                              void* d_out, int out_size) {
    (void)in_sizes; (void)n_in; (void)out_size;
    const float4* o0 = (const float4*)d_in[0];
    const float4* o1 = (const float4*)d_in[1];
    const float*  o2 = (const float*) d_in[2];
    const float4* tg = (const float4*)d_in[3];

    fused_kernel<<<GRID, THREADS>>>(o0, o1, tg, o2, (float*)d_out);
}